// round 7
// baseline (speedup 1.0000x reference)
#include <cuda_runtime.h>
#include <cstddef>
#include <cstdint>

namespace {

constexpr int B = 2, N = 512, C = 64, H = 8;
constexpr int THREADS = 256;            // 2 n-rows per thread
constexpr int SCH    = 16;              // channels per stage
constexpr int STAGES = 8;               // 4 q-stages + 4 k-stages
constexpr int CSTR   = 514;             // float4 stride between c4-chunk regions (bank-quad spread)
constexpr int BUF_F4 = 4 * CSTR;        // float4 slots per buffer (2056) = 32.9 KB
// dynamic smem: Ws[1024] | buf0 | buf1 | wsum[8*8]   (floats)
constexpr size_t SMEM_BYTES = (1024 + 2 * BUF_F4 * 4 + 8 * H) * sizeof(float);

#define FMA2(acc, a, b) \
    asm("fma.rn.f32x2 %0, %1, %2, %0;" : "+l"(acc) : "l"(a), "l"(b))

__device__ __forceinline__ unsigned long long pack2(float lo, float hi) {
    unsigned long long d;
    asm("mov.b64 %0, {%1, %2};" : "=l"(d) : "r"(__float_as_uint(lo)), "r"(__float_as_uint(hi)));
    return d;
}
__device__ __forceinline__ void unpack2(unsigned long long v, float& lo, float& hi) {
    unsigned int l, h;
    asm("mov.b64 {%0, %1}, %2;" : "=r"(l), "=r"(h) : "l"(v));
    lo = __uint_as_float(l);
    hi = __uint_as_float(h);
}
__device__ __forceinline__ uint32_t smem_u32(const void* p) {
    return (uint32_t)__cvta_generic_to_shared(p);
}
__device__ __forceinline__ void cp_async16(uint32_t dst, const void* src) {
    asm volatile("cp.async.cg.shared.global [%0], [%1], 16;" :: "r"(dst), "l"(src));
}

__global__ __launch_bounds__(THREADS, 3)
void mha_fused_kernel(const float* __restrict__ q,
                      const float* __restrict__ k,
                      const float* __restrict__ roi,
                      const float* __restrict__ W,
                      const float* __restrict__ bias,
                      float* __restrict__ out)
{
    extern __shared__ float smem[];
    float* Ws   = smem;                              // [c][h], 4 KB
    float4* ring = reinterpret_cast<float4*>(smem + 1024);   // 2 x BUF_F4 float4
    float* wsum = smem + 1024 + 2 * BUF_F4 * 4;      // [8][H]

    const int tid  = threadIdx.x;
    const int bm   = blockIdx.x;                     // b*N + m
    const int warp = tid >> 5;
    const int lane = tid & 31;

    const float* qb = q + (size_t)bm * N * C;
    const float* kb = k + (size_t)bm * N * C;

    // W[h][128] -> Ws[c][h]
    for (int i = tid; i < 128 * H; i += THREADS) {
        const int h = i >> 7, c = i & 127;
        Ws[c * H + h] = W[i];
    }

    // ---- stage issue: 16 channels x 512 rows; dst chunk-major [c4][row], stride CSTR ----
    // global mapping keeps warp on 8 consecutive rows (64B contiguous per row)
    auto issue_stage = [&](int s) {
        const float* src = (s < 4 ? qb + s * SCH : kb + (s - 4) * SCH);
        float4* dst = ring + (s & 1) * BUF_F4;
#pragma unroll
        for (int i = 0; i < 8; ++i) {
            const int idx = i * THREADS + tid;       // 0..2047
            const int row = idx >> 2, c4 = idx & 3;
            cp_async16(smem_u32(&dst[c4 * CSTR + row]),
                       src + (size_t)row * C + c4 * 4);
        }
        asm volatile("cp.async.commit_group;" ::: "memory");
    };

    issue_stage(0);

    unsigned long long acc0[4], acc1[4];
    acc0[0] = pack2(bias[0], bias[1]);
    acc0[1] = pack2(bias[2], bias[3]);
    acc0[2] = pack2(bias[4], bias[5]);
    acc0[3] = pack2(bias[6], bias[7]);
#pragma unroll
    for (int j = 0; j < 4; ++j) acc1[j] = acc0[j];

#pragma unroll
    for (int s = 0; s < STAGES; ++s) {
        asm volatile("cp.async.wait_group 0;" ::: "memory");
        __syncthreads();                            // stage s visible; stage s-1 readers done
        if (s + 1 < STAGES) issue_stage(s + 1);     // overlaps with compute below

        const float4* base = ring + (s & 1) * BUF_F4;
        const ulonglong2* wp = reinterpret_cast<const ulonglong2*>(&Ws[(s * SCH) * H]);

#pragma unroll
        for (int c4 = 0; c4 < 4; ++c4) {
            // conflict-free: consecutive lanes -> consecutive float4 slots
            const float4 v0 = base[c4 * CSTR + tid];
            const float4 v1 = base[c4 * CSTR + tid + 256];
            const float a0v[4] = {v0.x, v0.y, v0.z, v0.w};
            const float a1v[4] = {v1.x, v1.y, v1.z, v1.w};
#pragma unroll
            for (int cc = 0; cc < 4; ++cc) {
                const int c = c4 * 4 + cc;
                const ulonglong2 w01 = wp[c * 2];        // heads 0-3
                const ulonglong2 w45 = wp[c * 2 + 1];    // heads 4-7
                const unsigned long long a0 = pack2(a0v[cc], a0v[cc]);
                const unsigned long long a1 = pack2(a1v[cc], a1v[cc]);
                FMA2(acc0[0], a0, w01.x);
                FMA2(acc0[1], a0, w01.y);
                FMA2(acc0[2], a0, w45.x);
                FMA2(acc0[3], a0, w45.y);
                FMA2(acc1[0], a1, w01.x);
                FMA2(acc1[1], a1, w01.y);
                FMA2(acc1[2], a1, w45.x);
                FMA2(acc1[3], a1, w45.y);
            }
        }
    }

    // ---- epilogue: exp * roi for both rows ----
    float e0[H], e1[H], sums[H];
    {
        float a0[H], a1[H];
#pragma unroll
        for (int j = 0; j < 4; ++j) {
            unpack2(acc0[j], a0[2 * j], a0[2 * j + 1]);
            unpack2(acc1[j], a1[2 * j], a1[2 * j + 1]);
        }
        const float r0v = roi[(size_t)bm * N + tid];
        const float r1v = roi[(size_t)bm * N + tid + 256];
#pragma unroll
        for (int h = 0; h < H; ++h) {
            e0[h] = __expf(a0[h]) * r0v;
            e1[h] = __expf(a1[h]) * r1v;
            sums[h] = e0[h] + e1[h];
        }
    }

    // ---- block-wide row-sum over all 512 n ----
#pragma unroll
    for (int h = 0; h < H; ++h) {
        float s = sums[h];
#pragma unroll
        for (int off = 16; off > 0; off >>= 1)
            s += __shfl_xor_sync(0xffffffffu, s, off);
        sums[h] = s;
    }
    if (lane == 0) {
#pragma unroll
        for (int h = 0; h < H; ++h) wsum[warp * H + h] = sums[h];
    }
    __syncthreads();

    float inv[H];
#pragma unroll
    for (int h = 0; h < H; ++h) {
        float t = 0.f;
#pragma unroll
        for (int w = 0; w < 8; ++w) t += wsum[w * H + h];
        inv[h] = 1.0f / t;
    }

    // ---- normalize + store (2x STG.128 per row) ----
    {
        float* op = out + ((size_t)bm * N + tid) * H;
        float4 a, b2;
        a.x  = e0[0] * inv[0];  a.y  = e0[1] * inv[1];
        a.z  = e0[2] * inv[2];  a.w  = e0[3] * inv[3];
        b2.x = e0[4] * inv[4];  b2.y = e0[5] * inv[5];
        b2.z = e0[6] * inv[6];  b2.w = e0[7] * inv[7];
        *reinterpret_cast<float4*>(op)     = a;
        *reinterpret_cast<float4*>(op + 4) = b2;
    }
    {
        float* op = out + ((size_t)bm * N + tid + 256) * H;
        float4 a, b2;
        a.x  = e1[0] * inv[0];  a.y  = e1[1] * inv[1];
        a.z  = e1[2] * inv[2];  a.w  = e1[3] * inv[3];
        b2.x = e1[4] * inv[4];  b2.y = e1[5] * inv[5];
        b2.z = e1[6] * inv[6];  b2.w = e1[7] * inv[7];
        *reinterpret_cast<float4*>(op)     = a;
        *reinterpret_cast<float4*>(op + 4) = b2;
    }
}

} // namespace

extern "C" void kernel_launch(void* const* d_in, const int* in_sizes, int n_in,
                              void* d_out, int out_size)
{
    const float* q    = (const float*)d_in[0];
    const float* k    = (const float*)d_in[1];
    const float* roi  = (const float*)d_in[2];
    const float* W    = (const float*)d_in[3];
    const float* bias = (const float*)d_in[4];
    float* out        = (float*)d_out;

    (void)in_sizes; (void)n_in; (void)out_size;

    cudaFuncSetAttribute(mha_fused_kernel,
                         cudaFuncAttributeMaxDynamicSharedMemorySize,
                         (int)SMEM_BYTES);

    dim3 grid(B * N);     // one block per (b, m) row
    dim3 block(THREADS);
    mha_fused_kernel<<<grid, block, SMEM_BYTES>>>(q, k, roi, W, bias, out);
}

// round 9
// speedup vs baseline: 2.2318x; 2.2318x over previous
#include <cuda_runtime.h>
#include <cstddef>
#include <cstdint>

namespace {

constexpr int B = 2, N = 512, C = 64, H = 8;
constexpr int THREADS = 256;            // 2 n-rows per thread
constexpr int SCH    = 16;              // channels per stage
constexpr int STAGES = 8;               // 4 q-stages + 4 k-stages
constexpr int NBUF   = 3;               // ring depth
constexpr int BUF_F4 = 512 * 4;         // 2048 float4 = 32 KB per buffer (swizzled, no pad)
// dynamic smem: Ws[1024] | ring (3 x 8192 floats) | wsum[8*8]
constexpr size_t SMEM_BYTES = (1024 + NBUF * BUF_F4 * 4 + 8 * H) * sizeof(float);

#define FMA2(acc, a, b) \
    asm("fma.rn.f32x2 %0, %1, %2, %0;" : "+l"(acc) : "l"(a), "l"(b))

__device__ __forceinline__ unsigned long long pack2(float lo, float hi) {
    unsigned long long d;
    asm("mov.b64 %0, {%1, %2};" : "=l"(d) : "r"(__float_as_uint(lo)), "r"(__float_as_uint(hi)));
    return d;
}
__device__ __forceinline__ void unpack2(unsigned long long v, float& lo, float& hi) {
    unsigned int l, h;
    asm("mov.b64 {%0, %1}, %2;" : "=r"(l), "=r"(h) : "l"(v));
    lo = __uint_as_float(l);
    hi = __uint_as_float(h);
}
__device__ __forceinline__ uint32_t smem_u32(const void* p) {
    return (uint32_t)__cvta_generic_to_shared(p);
}
__device__ __forceinline__ void cp_async16(uint32_t dst, const void* src) {
    asm volatile("cp.async.cg.shared.global [%0], [%1], 16;" :: "r"(dst), "l"(src));
}

// swizzled float4 slot inside a buffer: conflict-free for both cp.async writes
// (within-row 64B permutation) and per-thread row reads (8 distinct bank-quads/phase)
__device__ __forceinline__ int slot_of(int row, int c4) {
    return row * 4 + (c4 ^ ((row >> 1) & 3));
}

__global__ __launch_bounds__(THREADS, 2)
void mha_fused_kernel(const float* __restrict__ q,
                      const float* __restrict__ k,
                      const float* __restrict__ roi,
                      const float* __restrict__ W,
                      const float* __restrict__ bias,
                      float* __restrict__ out)
{
    extern __shared__ float smem[];
    float* Ws = smem;                                         // [c][h], 4 KB
    float4* ring = reinterpret_cast<float4*>(smem + 1024);    // NBUF x BUF_F4
    float* wsum = smem + 1024 + NBUF * BUF_F4 * 4;            // [8][H]

    const int tid  = threadIdx.x;
    const int bm   = blockIdx.x;                              // b*N + m
    const int warp = tid >> 5;
    const int lane = tid & 31;

    const float* qb = q + (size_t)bm * N * C;
    const float* kb = k + (size_t)bm * N * C;

    // W[h][128] -> Ws[c][h]
    for (int i = tid; i < 128 * H; i += THREADS) {
        const int h = i >> 7, c = i & 127;
        Ws[c * H + h] = W[i];
    }

    // ---- stage issue: 16 channels x 512 rows ----
    auto issue_stage = [&](int s) {
        const float* src = (s < 4 ? qb + s * SCH : kb + (s - 4) * SCH);
        float4* dst = ring + (s % NBUF) * BUF_F4;
#pragma unroll
        for (int i = 0; i < 8; ++i) {
            const int idx = i * THREADS + tid;                // 0..2047
            const int row = idx >> 2, c4 = idx & 3;
            cp_async16(smem_u32(&dst[slot_of(row, c4)]),
                       src + (size_t)row * C + c4 * 4);
        }
        asm volatile("cp.async.commit_group;" ::: "memory");
    };

    issue_stage(0);
    issue_stage(1);

    unsigned long long acc0[4], acc1[4];
    acc0[0] = pack2(bias[0], bias[1]);
    acc0[1] = pack2(bias[2], bias[3]);
    acc0[2] = pack2(bias[4], bias[5]);
    acc0[3] = pack2(bias[6], bias[7]);
#pragma unroll
    for (int j = 0; j < 4; ++j) acc1[j] = acc0[j];

    const int sw = (tid >> 1) & 3;   // read-side swizzle (same for tid and tid+256)

#pragma unroll
    for (int s = 0; s < STAGES; ++s) {
        if (s < STAGES - 1) {
            asm volatile("cp.async.wait_group 1;" ::: "memory");  // stage s landed; s+1 may fly
        } else {
            asm volatile("cp.async.wait_group 0;" ::: "memory");  // last stage: drain all
        }
        __syncthreads();                           // data visible; buf (s+2)%3 readers done
        if (s + 2 < STAGES) issue_stage(s + 2);    // overlaps with compute below

        const float4* base = ring + (s % NBUF) * BUF_F4;
        const ulonglong2* wp = reinterpret_cast<const ulonglong2*>(&Ws[(s * SCH) * H]);

#pragma unroll
        for (int j = 0; j < 4; ++j) {
            const float4 v0 = base[tid * 4 + (j ^ sw)];
            const float4 v1 = base[(tid + 256) * 4 + (j ^ sw)];
            const float a0v[4] = {v0.x, v0.y, v0.z, v0.w};
            const float a1v[4] = {v1.x, v1.y, v1.z, v1.w};
#pragma unroll
            for (int cc = 0; cc < 4; ++cc) {
                const int c = j * 4 + cc;
                const ulonglong2 w01 = wp[c * 2];         // heads 0-3
                const ulonglong2 w45 = wp[c * 2 + 1];     // heads 4-7
                const unsigned long long a0 = pack2(a0v[cc], a0v[cc]);
                const unsigned long long a1 = pack2(a1v[cc], a1v[cc]);
                FMA2(acc0[0], a0, w01.x);
                FMA2(acc0[1], a0, w01.y);
                FMA2(acc0[2], a0, w45.x);
                FMA2(acc0[3], a0, w45.y);
                FMA2(acc1[0], a1, w01.x);
                FMA2(acc1[1], a1, w01.y);
                FMA2(acc1[2], a1, w45.x);
                FMA2(acc1[3], a1, w45.y);
            }
        }
    }

    // ---- epilogue: exp * roi for both rows ----
    float e0[H], e1[H], sums[H];
    {
        float a0[H], a1[H];
#pragma unroll
        for (int j = 0; j < 4; ++j) {
            unpack2(acc0[j], a0[2 * j], a0[2 * j + 1]);
            unpack2(acc1[j], a1[2 * j], a1[2 * j + 1]);
        }
        const float r0v = roi[(size_t)bm * N + tid];
        const float r1v = roi[(size_t)bm * N + tid + 256];
#pragma unroll
        for (int h = 0; h < H; ++h) {
            e0[h] = __expf(a0[h]) * r0v;
            e1[h] = __expf(a1[h]) * r1v;
            sums[h] = e0[h] + e1[h];
        }
    }

    // ---- block-wide row-sum over all 512 n ----
#pragma unroll
    for (int h = 0; h < H; ++h) {
        float s = sums[h];
#pragma unroll
        for (int off = 16; off > 0; off >>= 1)
            s += __shfl_xor_sync(0xffffffffu, s, off);
        sums[h] = s;
    }
    if (lane == 0) {
#pragma unroll
        for (int h = 0; h < H; ++h) wsum[warp * H + h] = sums[h];
    }
    __syncthreads();

    float inv[H];
#pragma unroll
    for (int h = 0; h < H; ++h) {
        float t = 0.f;
#pragma unroll
        for (int w = 0; w < 8; ++w) t += wsum[w * H + h];
        inv[h] = 1.0f / t;
    }

    // ---- normalize + store (2x STG.128 per row) ----
    {
        float* op = out + ((size_t)bm * N + tid) * H;
        float4 a, b2;
        a.x  = e0[0] * inv[0];  a.y  = e0[1] * inv[1];
        a.z  = e0[2] * inv[2];  a.w  = e0[3] * inv[3];
        b2.x = e0[4] * inv[4];  b2.y = e0[5] * inv[5];
        b2.z = e0[6] * inv[6];  b2.w = e0[7] * inv[7];
        *reinterpret_cast<float4*>(op)     = a;
        *reinterpret_cast<float4*>(op + 4) = b2;
    }
    {
        float* op = out + ((size_t)bm * N + tid + 256) * H;
        float4 a, b2;
        a.x  = e1[0] * inv[0];  a.y  = e1[1] * inv[1];
        a.z  = e1[2] * inv[2];  a.w  = e1[3] * inv[3];
        b2.x = e1[4] * inv[4];  b2.y = e1[5] * inv[5];
        b2.z = e1[6] * inv[6];  b2.w = e1[7] * inv[7];
        *reinterpret_cast<float4*>(op)     = a;
        *reinterpret_cast<float4*>(op + 4) = b2;
    }
}

} // namespace

extern "C" void kernel_launch(void* const* d_in, const int* in_sizes, int n_in,
                              void* d_out, int out_size)
{
    const float* q    = (const float*)d_in[0];
    const float* k    = (const float*)d_in[1];
    const float* roi  = (const float*)d_in[2];
    const float* W    = (const float*)d_in[3];
    const float* bias = (const float*)d_in[4];
    float* out        = (float*)d_out;

    (void)in_sizes; (void)n_in; (void)out_size;

    cudaFuncSetAttribute(mha_fused_kernel,
                         cudaFuncAttributeMaxDynamicSharedMemorySize,
                         (int)SMEM_BYTES);

    dim3 grid(B * N);     // one block per (b, m) row
    dim3 block(THREADS);
    mha_fused_kernel<<<grid, block, SMEM_BYTES>>>(q, k, roi, W, bias, out);
}